// round 2
// baseline (speedup 1.0000x reference)
#include <cuda_runtime.h>
#include <cuda_bf16.h>
#include <cstdint>

#define NN 100000
#define NE 3200000
#define NG 1024

// ---------------- scratch (device globals; no allocation allowed) ----------
__device__ __align__(256) float g_dis[NN];          // deg -> rsqrt(deg)
__device__ __align__(256) float g_agg[NN * 16];     // scatter target (3- or 16-wide)
__device__ __align__(256) float g_h32[NN * 32];     // h1
__device__ __align__(256) float g_t[NN * 16];       // transformed features pre-prop
__device__ __align__(256) float g_h16[NN * 16];     // h2 / h3
__device__ __align__(256) float g_pool[NG * 16];    // pooled
__device__ int g_ei64;                              // 1 if edge_index is int64
__device__ int g_b64;                               // 1 if batch is int64

// ---------------- index load that tolerates int32 or int64 -----------------
__device__ __forceinline__ int ldidx(const void* p, long long i, int is64) {
    if (is64) return (int)(((const long long*)p)[i]);
    return ((const int*)p)[i];
}

// ---------------- dtype detection ------------------------------------------
__global__ void detect_kernel(const void* ei, const void* batch) {
    if (threadIdx.x != 0 || blockIdx.x != 0) return;
    // edge_index values are uniform in [0,100000); if stored int32, reading
    // pairs through u64 almost surely yields a value > 2^32.
    const unsigned long long* pe = (const unsigned long long*)ei;
    int big = 0;
    for (int k = 0; k < 8; k++) if (pe[k] > 0xFFFFFFFFull) big = 1;
    g_ei64 = big ? 0 : 1;
    // batch is sorted; sample mid-array where values ~512 so int32-pair u64
    // reads are huge.
    const unsigned long long* pb = (const unsigned long long*)batch;
    int big2 = 0;
    for (int k = 0; k < 8; k++) if (pb[20000 + k] > 0xFFFFFFFFull) big2 = 1;
    g_b64 = big2 ? 0 : 1;
}

// ---------------- degree / norm --------------------------------------------
__global__ void init_dis_kernel() {
    int i = blockIdx.x * blockDim.x + threadIdx.x;
    if (i < NN) g_dis[i] = 1.0f;   // self-loop
}

__global__ void deg_kernel(const void* ei) {
    int e = blockIdx.x * blockDim.x + threadIdx.x;
    if (e >= NE) return;
    int is64 = g_ei64;
    int d = ldidx(ei, (long long)NE + e, is64);
    atomicAdd(&g_dis[d], 1.0f);
}

__global__ void rsqrt_kernel() {
    int i = blockIdx.x * blockDim.x + threadIdx.x;
    if (i < NN) g_dis[i] = rsqrtf(g_dis[i]);
}

// ---------------- layer 1 ----------------------------------------------------
// init agg (3-wide) with the self-loop term x * dis^2
__global__ void init3_kernel(const float* x) {
    int i = blockIdx.x * blockDim.x + threadIdx.x;
    if (i >= NN) return;
    float di = g_dis[i];
    float r = di * di;
    g_agg[3 * i + 0] = x[3 * i + 0] * r;
    g_agg[3 * i + 1] = x[3 * i + 1] * r;
    g_agg[3 * i + 2] = x[3 * i + 2] * r;
}

__global__ void prop3_kernel(const void* ei, const float* x) {
    int e = blockIdx.x * blockDim.x + threadIdx.x;
    if (e >= NE) return;
    int is64 = g_ei64;
    int s = ldidx(ei, e, is64);
    int d = ldidx(ei, (long long)NE + e, is64);
    float w = g_dis[s] * g_dis[d];
    const float* xs = x + 3 * s;
    float* ad = g_agg + 3 * d;
    atomicAdd(ad + 0, xs[0] * w);
    atomicAdd(ad + 1, xs[1] * w);
    atomicAdd(ad + 2, xs[2] * w);
}

// h1 = relu(agg @ W1^T + b1)  [N,3] -> [N,32]; then t = h1 @ W2^T [N,32]->[N,16]
// fused: also seeds next agg with t * dis^2
__global__ void xform12_kernel(const float* W1, const float* b1, const float* W2) {
    int i = blockIdx.x * blockDim.x + threadIdx.x;
    if (i >= NN) return;
    float p0 = g_agg[3 * i + 0];
    float p1 = g_agg[3 * i + 1];
    float p2 = g_agg[3 * i + 2];
    float h[32];
#pragma unroll
    for (int o = 0; o < 32; o++) {
        float v = __ldg(&b1[o])
                + p0 * __ldg(&W1[o * 3 + 0])
                + p1 * __ldg(&W1[o * 3 + 1])
                + p2 * __ldg(&W1[o * 3 + 2]);
        h[o] = fmaxf(v, 0.0f);
    }
    float di = g_dis[i];
    float r = di * di;
#pragma unroll
    for (int o = 0; o < 16; o++) {
        float v = 0.0f;
#pragma unroll
        for (int k = 0; k < 32; k++) v += h[k] * __ldg(&W2[o * 32 + k]);
        g_t[16 * i + o] = v;
        g_agg[16 * i + o] = v * r;     // self-loop seed; prop16 adds on top
    }
}

// 16-wide scatter: agg[dst] += t[src] * dis[s]*dis[d], via red.v4 (no return)
__global__ void prop16_kernel(const void* ei) {
    int e = blockIdx.x * blockDim.x + threadIdx.x;
    if (e >= NE) return;
    int is64 = g_ei64;
    int s = ldidx(ei, e, is64);
    int d = ldidx(ei, (long long)NE + e, is64);
    float w = g_dis[s] * g_dis[d];
    const float4* src = (const float4*)(g_t + 16 * s);
    float* dstp = g_agg + 16 * d;
#pragma unroll
    for (int j = 0; j < 4; j++) {
        float4 v = src[j];
        asm volatile("red.global.add.v4.f32 [%0], {%1,%2,%3,%4};"
                     :: "l"(dstp + 4 * j),
                        "f"(v.x * w), "f"(v.y * w), "f"(v.z * w), "f"(v.w * w)
                     : "memory");
    }
}

// h = relu(agg + b); then t = h @ W^T; seeds agg with t*dis^2 for next prop.
// store_h: also store h into g_h16 (needed for final layer's pooling input).
template <int STORE_H, int DO_XFORM>
__global__ void combine_xform_kernel(const float* b, const float* W) {
    int i = blockIdx.x * blockDim.x + threadIdx.x;
    if (i >= NN) return;
    float h[16];
#pragma unroll
    for (int o = 0; o < 16; o++)
        h[o] = fmaxf(g_agg[16 * i + o] + __ldg(&b[o]), 0.0f);
    if (STORE_H) {
#pragma unroll
        for (int o = 0; o < 16; o++) g_h16[16 * i + o] = h[o];
    }
    if (DO_XFORM) {
        float di = g_dis[i];
        float r = di * di;
#pragma unroll
        for (int o = 0; o < 16; o++) {
            float v = 0.0f;
#pragma unroll
            for (int k = 0; k < 16; k++) v += h[k] * __ldg(&W[o * 16 + k]);
            g_t[16 * i + o] = v;
            g_agg[16 * i + o] = v * r;
        }
    }
}

// ---------------- pooling: one warp per graph, batch is sorted --------------
__global__ void pool_kernel(const void* batch) {
    int gwarp = (blockIdx.x * blockDim.x + threadIdx.x) >> 5;
    int lane = threadIdx.x & 31;
    if (gwarp >= NG) return;
    int is64 = g_b64;
    int lo = 0, hi = NN;
    while (lo < hi) { int m = (lo + hi) >> 1; if (ldidx(batch, m, is64) < gwarp) lo = m + 1; else hi = m; }
    int start = lo;
    hi = NN;
    while (lo < hi) { int m = (lo + hi) >> 1; if (ldidx(batch, m, is64) < gwarp + 1) lo = m + 1; else hi = m; }
    int end = lo;

    int ch = lane & 15;
    int off = lane >> 4;            // 0 or 1: which node of the pair
    float acc = 0.0f;
    for (int n = start + off; n < end; n += 2)
        acc += g_h16[n * 16 + ch];
    acc += __shfl_down_sync(0xFFFFFFFFu, acc, 16);
    if (lane < 16) g_pool[gwarp * 16 + lane] = acc;
}

// ---------------- head: embedding = pool@We^T+be ; out = relu(emb)@Wc^T+bc --
__global__ void head_kernel(const float* We, const float* be,
                            const float* Wc, const float* bc, float* out) {
    int g = blockIdx.x * blockDim.x + threadIdx.x;
    if (g >= NG) return;
    float p[16];
#pragma unroll
    for (int k = 0; k < 16; k++) p[k] = g_pool[g * 16 + k];
    float dot = 0.0f;
#pragma unroll
    for (int o = 0; o < 16; o++) {
        float v = __ldg(&be[o]);
#pragma unroll
        for (int k = 0; k < 16; k++) v += p[k] * __ldg(&We[o * 16 + k]);
        out[g * 16 + o] = v;                       // embedding
        dot += fmaxf(v, 0.0f) * __ldg(&Wc[o]);
    }
    out[NG * 16 + g] = dot + __ldg(&bc[0]);        // final scalar
}

// ---------------- launch ----------------------------------------------------
extern "C" void kernel_launch(void* const* d_in, const int* in_sizes, int n_in,
                              void* d_out, int out_size) {
    const float* x   = (const float*)d_in[0];
    const void*  ei  = d_in[1];
    const void*  bat = d_in[2];
    const float* W1 = (const float*)d_in[3];
    const float* b1 = (const float*)d_in[4];
    const float* W2 = (const float*)d_in[5];
    const float* b2 = (const float*)d_in[6];
    const float* W3 = (const float*)d_in[7];
    const float* b3 = (const float*)d_in[8];
    const float* We = (const float*)d_in[9];
    const float* be = (const float*)d_in[10];
    const float* Wc = (const float*)d_in[11];
    const float* bc = (const float*)d_in[12];
    float* out = (float*)d_out;

    const int TB = 256;
    const int gN  = (NN + TB - 1) / TB;
    const int gE  = (NE + TB - 1) / TB;

    detect_kernel<<<1, 32>>>(ei, bat);
    init_dis_kernel<<<gN, TB>>>();
    deg_kernel<<<gE, TB>>>(ei);
    rsqrt_kernel<<<gN, TB>>>();

    // layer 1: propagate raw 3-dim x (agg seeded with self-loop term),
    // then fused transform 3->32->16 which also seeds the 16-wide agg.
    init3_kernel<<<gN, TB>>>(x);
    prop3_kernel<<<gE, TB>>>(ei, x);
    xform12_kernel<<<gN, TB>>>(W1, b1, W2);

    // layer 2: propagate 16-wide, combine + transform 16->16 (seeds agg again)
    prop16_kernel<<<gE, TB>>>(ei);
    combine_xform_kernel<0, 1><<<gN, TB>>>(b2, W3);

    // layer 3: propagate 16-wide, combine (store h for pooling)
    prop16_kernel<<<gE, TB>>>(ei);
    combine_xform_kernel<1, 0><<<gN, TB>>>(b3, nullptr);

    // pooling (one warp per graph) + heads
    pool_kernel<<<(NG * 32 + TB - 1) / TB, TB>>>(bat);
    head_kernel<<<(NG + TB - 1) / TB, TB>>>(We, be, Wc, bc, out);
}

// round 3
// speedup vs baseline: 1.2981x; 1.2981x over previous
#include <cuda_runtime.h>
#include <cuda_bf16.h>
#include <cstdint>

#define NN 100000
#define NE 3200000
#define NG 1024

// ---------------- scratch (device globals; no allocation allowed) ----------
__device__ __align__(256) float g_dis[NN];           // deg -> rsqrt(deg)
__device__ __align__(256) float4 g_y4[NN];           // dis*x padded to 4-wide
__device__ __align__(256) float4 g_agg4[NN];         // layer-1 scatter target
__device__ __align__(256) float g_agg[NN * 16];      // 16-wide scatter target
__device__ __align__(256) float g_t[NN * 16];        // pre-scaled features t' = dis*t
__device__ __align__(256) float g_h16[NN * 16];      // h3 (pooling input)
__device__ __align__(256) float g_pool[NG * 16];     // pooled
__device__ int g_ei64;                               // 1 if edge_index is int64
__device__ int g_b64;                                // 1 if batch is int64

// ---------------- index load that tolerates int32 or int64 -----------------
__device__ __forceinline__ int ldidx(const void* p, long long i, int is64) {
    if (is64) return (int)(((const long long*)p)[i]);
    return ((const int*)p)[i];
}

// ---------------- dtype detection ------------------------------------------
__global__ void detect_kernel(const void* ei, const void* batch) {
    if (threadIdx.x != 0 || blockIdx.x != 0) return;
    const unsigned long long* pe = (const unsigned long long*)ei;
    int big = 0;
    for (int k = 0; k < 8; k++) if (pe[k] > 0xFFFFFFFFull) big = 1;
    g_ei64 = big ? 0 : 1;
    const unsigned long long* pb = (const unsigned long long*)batch;
    int big2 = 0;
    for (int k = 0; k < 8; k++) if (pb[20000 + k] > 0xFFFFFFFFull) big2 = 1;
    g_b64 = big2 ? 0 : 1;
}

// ---------------- degree / norm --------------------------------------------
__global__ void init_dis_kernel() {
    int i = blockIdx.x * blockDim.x + threadIdx.x;
    if (i < NN) g_dis[i] = 1.0f;   // self-loop
}

__global__ void deg_kernel(const void* ei) {
    int e = blockIdx.x * blockDim.x + threadIdx.x;
    if (e >= NE) return;
    int d = ldidx(ei, (long long)NE + e, g_ei64);
    atomicAdd(&g_dis[d], 1.0f);
}

// dis = rsqrt(deg); y = dis*x (padded float4); seed agg4 with y (self-loop)
__global__ void prep_kernel(const float* x) {
    int i = blockIdx.x * blockDim.x + threadIdx.x;
    if (i >= NN) return;
    float di = rsqrtf(g_dis[i]);
    g_dis[i] = di;
    float4 y;
    y.x = di * x[3 * i + 0];
    y.y = di * x[3 * i + 1];
    y.z = di * x[3 * i + 2];
    y.w = 0.0f;
    g_y4[i] = y;
    g_agg4[i] = y;
}

// layer-1 scatter: agg4[dst] += y[src]   (unweighted; dis folded into y / combine)
__global__ void prop4_kernel(const void* ei) {
    int e = blockIdx.x * blockDim.x + threadIdx.x;
    if (e >= NE) return;
    int is64 = g_ei64;
    int s = ldidx(ei, e, is64);
    int d = ldidx(ei, (long long)NE + e, is64);
    float4 v = g_y4[s];
    asm volatile("red.global.add.v4.f32 [%0], {%1,%2,%3,%4};"
                 :: "l"(&g_agg4[d]), "f"(v.x), "f"(v.y), "f"(v.z), "f"(v.w)
                 : "memory");
}

// p = dis[i]*agg4[i]; h1 = relu(p@W1^T + b1) [3->32]; t = h1@W2^T [32->16];
// store t' = dis*t and seed 16-wide agg with t'.
__global__ void xform12_kernel(const float* W1, const float* b1, const float* W2) {
    int i = blockIdx.x * blockDim.x + threadIdx.x;
    if (i >= NN) return;
    float di = g_dis[i];
    float4 a = g_agg4[i];
    float p0 = di * a.x, p1 = di * a.y, p2 = di * a.z;
    float h[32];
#pragma unroll
    for (int o = 0; o < 32; o++) {
        float v = __ldg(&b1[o])
                + p0 * __ldg(&W1[o * 3 + 0])
                + p1 * __ldg(&W1[o * 3 + 1])
                + p2 * __ldg(&W1[o * 3 + 2]);
        h[o] = fmaxf(v, 0.0f);
    }
#pragma unroll
    for (int o = 0; o < 16; o++) {
        float v = 0.0f;
#pragma unroll
        for (int k = 0; k < 32; k++) v += h[k] * __ldg(&W2[o * 32 + k]);
        float tp = di * v;                 // t' = dis * t
        g_t[16 * i + o] = tp;
        g_agg[16 * i + o] = tp;            // self-loop seed
    }
}

// 16-wide unweighted scatter: agg[dst] += t'[src]
__global__ void prop16_kernel(const void* ei) {
    int e = blockIdx.x * blockDim.x + threadIdx.x;
    if (e >= NE) return;
    int is64 = g_ei64;
    int s = ldidx(ei, e, is64);
    int d = ldidx(ei, (long long)NE + e, is64);
    const float4* src = (const float4*)(g_t + 16 * s);
    float* dstp = g_agg + 16 * d;
#pragma unroll
    for (int j = 0; j < 4; j++) {
        float4 v = src[j];
        asm volatile("red.global.add.v4.f32 [%0], {%1,%2,%3,%4};"
                     :: "l"(dstp + 4 * j),
                        "f"(v.x), "f"(v.y), "f"(v.z), "f"(v.w)
                     : "memory");
    }
}

// h = relu(dis[i]*agg + b); optionally store h (pooling input); optionally
// t = h@W^T, store t' = dis*t and re-seed agg.
template <int STORE_H, int DO_XFORM>
__global__ void combine_xform_kernel(const float* b, const float* W) {
    int i = blockIdx.x * blockDim.x + threadIdx.x;
    if (i >= NN) return;
    float di = g_dis[i];
    float h[16];
#pragma unroll
    for (int o = 0; o < 16; o++)
        h[o] = fmaxf(di * g_agg[16 * i + o] + __ldg(&b[o]), 0.0f);
    if (STORE_H) {
#pragma unroll
        for (int o = 0; o < 16; o++) g_h16[16 * i + o] = h[o];
    }
    if (DO_XFORM) {
#pragma unroll
        for (int o = 0; o < 16; o++) {
            float v = 0.0f;
#pragma unroll
            for (int k = 0; k < 16; k++) v += h[k] * __ldg(&W[o * 16 + k]);
            float tp = di * v;
            g_t[16 * i + o] = tp;
            g_agg[16 * i + o] = tp;
        }
    }
}

// ---------------- pooling: one warp per graph, batch is sorted --------------
__global__ void pool_kernel(const void* batch) {
    int gwarp = (blockIdx.x * blockDim.x + threadIdx.x) >> 5;
    int lane = threadIdx.x & 31;
    if (gwarp >= NG) return;
    int is64 = g_b64;
    int lo = 0, hi = NN;
    while (lo < hi) { int m = (lo + hi) >> 1; if (ldidx(batch, m, is64) < gwarp) lo = m + 1; else hi = m; }
    int start = lo;
    hi = NN;
    while (lo < hi) { int m = (lo + hi) >> 1; if (ldidx(batch, m, is64) < gwarp + 1) lo = m + 1; else hi = m; }
    int end = lo;

    int ch = lane & 15;
    int off = lane >> 4;
    float acc = 0.0f;
    for (int n = start + off; n < end; n += 2)
        acc += g_h16[n * 16 + ch];
    acc += __shfl_down_sync(0xFFFFFFFFu, acc, 16);
    if (lane < 16) g_pool[gwarp * 16 + lane] = acc;
}

// ---------------- head ------------------------------------------------------
__global__ void head_kernel(const float* We, const float* be,
                            const float* Wc, const float* bc, float* out) {
    int g = blockIdx.x * blockDim.x + threadIdx.x;
    if (g >= NG) return;
    float p[16];
#pragma unroll
    for (int k = 0; k < 16; k++) p[k] = g_pool[g * 16 + k];
    float dot = 0.0f;
#pragma unroll
    for (int o = 0; o < 16; o++) {
        float v = __ldg(&be[o]);
#pragma unroll
        for (int k = 0; k < 16; k++) v += p[k] * __ldg(&We[o * 16 + k]);
        out[g * 16 + o] = v;                       // embedding
        dot += fmaxf(v, 0.0f) * __ldg(&Wc[o]);
    }
    out[NG * 16 + g] = dot + __ldg(&bc[0]);        // final scalar
}

// ---------------- launch ----------------------------------------------------
extern "C" void kernel_launch(void* const* d_in, const int* in_sizes, int n_in,
                              void* d_out, int out_size) {
    const float* x   = (const float*)d_in[0];
    const void*  ei  = d_in[1];
    const void*  bat = d_in[2];
    const float* W1 = (const float*)d_in[3];
    const float* b1 = (const float*)d_in[4];
    const float* W2 = (const float*)d_in[5];
    const float* b2 = (const float*)d_in[6];
    const float* W3 = (const float*)d_in[7];
    const float* b3 = (const float*)d_in[8];
    const float* We = (const float*)d_in[9];
    const float* be = (const float*)d_in[10];
    const float* Wc = (const float*)d_in[11];
    const float* bc = (const float*)d_in[12];
    float* out = (float*)d_out;

    const int TB = 256;
    const int gN = (NN + TB - 1) / TB;
    const int gE = (NE + TB - 1) / TB;

    detect_kernel<<<1, 32>>>(ei, bat);
    init_dis_kernel<<<gN, TB>>>();
    deg_kernel<<<gE, TB>>>(ei);

    // layer 1 (commuted): scatter pre-scaled raw features, transform after
    prep_kernel<<<gN, TB>>>(x);
    prop4_kernel<<<gE, TB>>>(ei);
    xform12_kernel<<<gN, TB>>>(W1, b1, W2);

    // layer 2
    prop16_kernel<<<gE, TB>>>(ei);
    combine_xform_kernel<0, 1><<<gN, TB>>>(b2, W3);

    // layer 3
    prop16_kernel<<<gE, TB>>>(ei);
    combine_xform_kernel<1, 0><<<gN, TB>>>(b3, nullptr);

    // pooling + heads
    pool_kernel<<<(NG * 32 + TB - 1) / TB, TB>>>(bat);
    head_kernel<<<(NG + TB - 1) / TB, TB>>>(We, be, Wc, bc, out);
}

// round 4
// speedup vs baseline: 1.9529x; 1.5044x over previous
#include <cuda_runtime.h>
#include <cuda_bf16.h>
#include <cstdint>

#define NN 100000
#define NE 3200000
#define NG 1024
#define NB_SCAN ((NN + 255) / 256)   // 391 blocks in node-scan

// ---------------- scratch (device globals; no allocation allowed) ----------
__device__ __align__(256) float g_dis[NN];          // rsqrt(deg)
__device__ __align__(256) float4 g_y4[NN];          // dis*x padded to 4-wide
__device__ __align__(256) float4 g_agg4[NN];        // layer-1 gather output
__device__ __align__(256) float g_agg[NN * 16];     // 16-wide gather output
__device__ __align__(256) float g_t[NN * 16];       // pre-scaled features t' = dis*t
__device__ __align__(256) float g_h16[NN * 16];     // h3 (pooling input)
__device__ __align__(256) float g_pool[NG * 16];    // pooled
__device__ __align__(256) int g_cnt[NN];            // in-degree (excl self)
__device__ __align__(256) int g_rowptr[NN];         // CSR row starts
__device__ __align__(256) int g_cursor[NN];         // fill cursors
__device__ __align__(256) int g_csr_src[NE];        // CSR src indices
__device__ __align__(256) int g_bsum[NB_SCAN];      // per-block sums
__device__ __align__(256) int g_boff[NB_SCAN];      // per-block offsets
__device__ int g_ei64;
__device__ int g_b64;

// ---------------- index load that tolerates int32 or int64 -----------------
__device__ __forceinline__ int ldidx(const void* p, long long i, int is64) {
    if (is64) return (int)(((const long long*)p)[i]);
    return ((const int*)p)[i];
}

// ---------------- dtype detection ------------------------------------------
__global__ void detect_kernel(const void* ei, const void* batch) {
    if (threadIdx.x != 0 || blockIdx.x != 0) return;
    const unsigned long long* pe = (const unsigned long long*)ei;
    int big = 0;
    for (int k = 0; k < 8; k++) if (pe[k] > 0xFFFFFFFFull) big = 1;
    g_ei64 = big ? 0 : 1;
    const unsigned long long* pb = (const unsigned long long*)batch;
    int big2 = 0;
    for (int k = 0; k < 8; k++) if (pb[20000 + k] > 0xFFFFFFFFull) big2 = 1;
    g_b64 = big2 ? 0 : 1;
}

// ---------------- CSR build -------------------------------------------------
__global__ void zero_cnt_kernel() {
    int i = blockIdx.x * blockDim.x + threadIdx.x;
    if (i < NN) g_cnt[i] = 0;
}

__global__ void hist_kernel(const void* ei) {
    int e = blockIdx.x * blockDim.x + threadIdx.x;
    if (e >= NE) return;
    int d = ldidx(ei, (long long)NE + e, g_ei64);
    atomicAdd(&g_cnt[d], 1);
}

// per-block sums of g_cnt
__global__ void scan1_kernel() {
    __shared__ int sh[256];
    int i = blockIdx.x * 256 + threadIdx.x;
    int v = (i < NN) ? g_cnt[i] : 0;
    sh[threadIdx.x] = v;
    __syncthreads();
    for (int s = 128; s > 0; s >>= 1) {
        if (threadIdx.x < s) sh[threadIdx.x] += sh[threadIdx.x + s];
        __syncthreads();
    }
    if (threadIdx.x == 0) g_bsum[blockIdx.x] = sh[0];
}

// exclusive scan of block sums (single block, 512 threads, NB_SCAN<=512)
__global__ void scan2_kernel() {
    __shared__ int a[512], b[512];
    int t = threadIdx.x;
    int v = (t < NB_SCAN) ? g_bsum[t] : 0;
    a[t] = v;
    __syncthreads();
    int* in = a; int* out = b;
    for (int s = 1; s < 512; s <<= 1) {
        out[t] = in[t] + ((t >= s) ? in[t - s] : 0);
        __syncthreads();
        int* tmp = in; in = out; out = tmp;
    }
    if (t < NB_SCAN) g_boff[t] = in[t] - v;   // exclusive
}

// rowptr = boff[b] + exclusive-within-block; cursor = rowptr; dis = rsqrt(cnt+1)
__global__ void scan3_kernel() {
    __shared__ int a[256], b[256];
    int t = threadIdx.x;
    int i = blockIdx.x * 256 + t;
    int v = (i < NN) ? g_cnt[i] : 0;
    a[t] = v;
    __syncthreads();
    int* in = a; int* out = b;
    for (int s = 1; s < 256; s <<= 1) {
        out[t] = in[t] + ((t >= s) ? in[t - s] : 0);
        __syncthreads();
        int* tmp = in; in = out; out = tmp;
    }
    if (i < NN) {
        int rp = g_boff[blockIdx.x] + in[t] - v;
        g_rowptr[i] = rp;
        g_cursor[i] = rp;
        g_dis[i] = rsqrtf((float)(v + 1));
    }
}

__global__ void fill_kernel(const void* ei) {
    int e = blockIdx.x * blockDim.x + threadIdx.x;
    if (e >= NE) return;
    int is64 = g_ei64;
    int s = ldidx(ei, e, is64);
    int d = ldidx(ei, (long long)NE + e, is64);
    int pos = atomicAdd(&g_cursor[d], 1);
    g_csr_src[pos] = s;
}

// ---------------- node prep -------------------------------------------------
// y = dis*x (padded float4)
__global__ void prep_kernel(const float* x) {
    int i = blockIdx.x * blockDim.x + threadIdx.x;
    if (i >= NN) return;
    float di = g_dis[i];
    float4 y;
    y.x = di * x[3 * i + 0];
    y.y = di * x[3 * i + 1];
    y.z = di * x[3 * i + 2];
    y.w = 0.0f;
    g_y4[i] = y;
}

// ---------------- gathers (warp per node, no atomics) -----------------------
__global__ void gather4_kernel() {
    int node = (blockIdx.x * blockDim.x + threadIdx.x) >> 5;
    int lane = threadIdx.x & 31;
    if (node >= NN) return;
    int base = g_rowptr[node];
    int n = g_cnt[node];
    float4 acc = make_float4(0.f, 0.f, 0.f, 0.f);
    for (int e = lane; e < n; e += 32) {
        int s = g_csr_src[base + e];
        float4 v = g_y4[s];
        acc.x += v.x; acc.y += v.y; acc.z += v.z;
    }
#pragma unroll
    for (int s = 16; s > 0; s >>= 1) {
        acc.x += __shfl_xor_sync(0xFFFFFFFFu, acc.x, s);
        acc.y += __shfl_xor_sync(0xFFFFFFFFu, acc.y, s);
        acc.z += __shfl_xor_sync(0xFFFFFFFFu, acc.z, s);
    }
    if (lane == 0) {
        float4 self = g_y4[node];
        acc.x += self.x; acc.y += self.y; acc.z += self.z; acc.w = 0.f;
        g_agg4[node] = acc;
    }
}

// 16-wide gather: agg[i] = sum_{src in-edges} t'[src] + t'[i]
__global__ void gather16_kernel() {
    int node = (blockIdx.x * blockDim.x + threadIdx.x) >> 5;
    int lane = threadIdx.x & 31;
    if (node >= NN) return;
    int base = g_rowptr[node];
    int n = g_cnt[node];
    int grp = lane >> 2;     // 8 edge groups
    int j = lane & 3;        // float4 component block
    float4 acc = make_float4(0.f, 0.f, 0.f, 0.f);
    for (int e = grp; e < n; e += 8) {
        int s = g_csr_src[base + e];
        float4 v = *(const float4*)(g_t + 16 * s + 4 * j);
        acc.x += v.x; acc.y += v.y; acc.z += v.z; acc.w += v.w;
    }
    // reduce across the 8 groups (lanes with equal j)
#pragma unroll
    for (int s = 4; s < 32; s <<= 1) {
        acc.x += __shfl_xor_sync(0xFFFFFFFFu, acc.x, s);
        acc.y += __shfl_xor_sync(0xFFFFFFFFu, acc.y, s);
        acc.z += __shfl_xor_sync(0xFFFFFFFFu, acc.z, s);
        acc.w += __shfl_xor_sync(0xFFFFFFFFu, acc.w, s);
    }
    if (lane < 4) {
        float4 self = *(const float4*)(g_t + 16 * node + 4 * j);
        acc.x += self.x; acc.y += self.y; acc.z += self.z; acc.w += self.w;
        *(float4*)(g_agg + 16 * node + 4 * j) = acc;
    }
}

// ---------------- transforms -------------------------------------------------
// p = dis*agg4; h1 = relu(p@W1^T+b1) [3->32]; t = h1@W2^T [32->16]; t' = dis*t
__global__ void xform12_kernel(const float* W1, const float* b1, const float* W2) {
    int i = blockIdx.x * blockDim.x + threadIdx.x;
    if (i >= NN) return;
    float di = g_dis[i];
    float4 a = g_agg4[i];
    float p0 = di * a.x, p1 = di * a.y, p2 = di * a.z;
    float h[32];
#pragma unroll
    for (int o = 0; o < 32; o++) {
        float v = __ldg(&b1[o])
                + p0 * __ldg(&W1[o * 3 + 0])
                + p1 * __ldg(&W1[o * 3 + 1])
                + p2 * __ldg(&W1[o * 3 + 2]);
        h[o] = fmaxf(v, 0.0f);
    }
#pragma unroll
    for (int o = 0; o < 16; o++) {
        float v = 0.0f;
#pragma unroll
        for (int k = 0; k < 32; k++) v += h[k] * __ldg(&W2[o * 32 + k]);
        g_t[16 * i + o] = di * v;
    }
}

// h = relu(dis*agg + b); optional store h; optional t = h@W^T, t' = dis*t
template <int STORE_H, int DO_XFORM>
__global__ void combine_xform_kernel(const float* b, const float* W) {
    int i = blockIdx.x * blockDim.x + threadIdx.x;
    if (i >= NN) return;
    float di = g_dis[i];
    float h[16];
#pragma unroll
    for (int o = 0; o < 16; o++)
        h[o] = fmaxf(di * g_agg[16 * i + o] + __ldg(&b[o]), 0.0f);
    if (STORE_H) {
#pragma unroll
        for (int o = 0; o < 16; o++) g_h16[16 * i + o] = h[o];
    }
    if (DO_XFORM) {
#pragma unroll
        for (int o = 0; o < 16; o++) {
            float v = 0.0f;
#pragma unroll
            for (int k = 0; k < 16; k++) v += h[k] * __ldg(&W[o * 16 + k]);
            g_t[16 * i + o] = di * v;
        }
    }
}

// ---------------- pooling: one warp per graph, batch is sorted --------------
__global__ void pool_kernel(const void* batch) {
    int gwarp = (blockIdx.x * blockDim.x + threadIdx.x) >> 5;
    int lane = threadIdx.x & 31;
    if (gwarp >= NG) return;
    int is64 = g_b64;
    int lo = 0, hi = NN;
    while (lo < hi) { int m = (lo + hi) >> 1; if (ldidx(batch, m, is64) < gwarp) lo = m + 1; else hi = m; }
    int start = lo;
    hi = NN;
    while (lo < hi) { int m = (lo + hi) >> 1; if (ldidx(batch, m, is64) < gwarp + 1) lo = m + 1; else hi = m; }
    int end = lo;

    int ch = lane & 15;
    int off = lane >> 4;
    float acc = 0.0f;
    for (int n = start + off; n < end; n += 2)
        acc += g_h16[n * 16 + ch];
    acc += __shfl_down_sync(0xFFFFFFFFu, acc, 16);
    if (lane < 16) g_pool[gwarp * 16 + lane] = acc;
}

// ---------------- head ------------------------------------------------------
__global__ void head_kernel(const float* We, const float* be,
                            const float* Wc, const float* bc, float* out) {
    int g = blockIdx.x * blockDim.x + threadIdx.x;
    if (g >= NG) return;
    float p[16];
#pragma unroll
    for (int k = 0; k < 16; k++) p[k] = g_pool[g * 16 + k];
    float dot = 0.0f;
#pragma unroll
    for (int o = 0; o < 16; o++) {
        float v = __ldg(&be[o]);
#pragma unroll
        for (int k = 0; k < 16; k++) v += p[k] * __ldg(&We[o * 16 + k]);
        out[g * 16 + o] = v;
        dot += fmaxf(v, 0.0f) * __ldg(&Wc[o]);
    }
    out[NG * 16 + g] = dot + __ldg(&bc[0]);
}

// ---------------- launch ----------------------------------------------------
extern "C" void kernel_launch(void* const* d_in, const int* in_sizes, int n_in,
                              void* d_out, int out_size) {
    const float* x   = (const float*)d_in[0];
    const void*  ei  = d_in[1];
    const void*  bat = d_in[2];
    const float* W1 = (const float*)d_in[3];
    const float* b1 = (const float*)d_in[4];
    const float* W2 = (const float*)d_in[5];
    const float* b2 = (const float*)d_in[6];
    const float* W3 = (const float*)d_in[7];
    const float* b3 = (const float*)d_in[8];
    const float* We = (const float*)d_in[9];
    const float* be = (const float*)d_in[10];
    const float* Wc = (const float*)d_in[11];
    const float* bc = (const float*)d_in[12];
    float* out = (float*)d_out;

    const int TB = 256;
    const int gN = (NN + TB - 1) / TB;           // node grid
    const int gE = (NE + TB - 1) / TB;           // edge grid
    const int gW = (NN * 32 + TB - 1) / TB;      // warp-per-node grid

    detect_kernel<<<1, 32>>>(ei, bat);

    // CSR build (also yields dis)
    zero_cnt_kernel<<<gN, TB>>>();
    hist_kernel<<<gE, TB>>>(ei);
    scan1_kernel<<<NB_SCAN, 256>>>();
    scan2_kernel<<<1, 512>>>();
    scan3_kernel<<<NB_SCAN, 256>>>();
    fill_kernel<<<gE, TB>>>(ei);

    // layer 1: commuted propagation of pre-scaled raw features
    prep_kernel<<<gN, TB>>>(x);
    gather4_kernel<<<gW, TB>>>();
    xform12_kernel<<<gN, TB>>>(W1, b1, W2);

    // layer 2
    gather16_kernel<<<gW, TB>>>();
    combine_xform_kernel<0, 1><<<gN, TB>>>(b2, W3);

    // layer 3
    gather16_kernel<<<gW, TB>>>();
    combine_xform_kernel<1, 0><<<gN, TB>>>(b3, nullptr);

    // pooling + heads
    pool_kernel<<<(NG * 32 + TB - 1) / TB, TB>>>(bat);
    head_kernel<<<(NG + TB - 1) / TB, TB>>>(We, be, Wc, bc, out);
}

// round 5
// speedup vs baseline: 2.0063x; 1.0273x over previous
#include <cuda_runtime.h>
#include <cuda_bf16.h>
#include <cstdint>

#define NN 100000
#define NE 3200000
#define NG 1024
#define NB_SCAN ((NN + 255) / 256)   // 391 blocks in node-scan

// ---------------- scratch (device globals; no allocation allowed) ----------
__device__ __align__(256) float g_dis[NN];          // rsqrt(deg)
__device__ __align__(256) float4 g_y4[NN];          // dis*x padded to 4-wide
__device__ __align__(256) float4 g_agg4[NN];        // layer-1 gather output
__device__ __align__(256) float g_agg[NN * 16];     // 16-wide gather output
__device__ __align__(256) float g_t[NN * 16];       // pre-scaled features t' = dis*t
__device__ __align__(256) float g_pool[NG * 16];    // pooled (atomic target)
__device__ __align__(256) int g_cnt[NN];            // in-degree (excl self)
__device__ __align__(256) int g_rowptr[NN];         // CSR row starts
__device__ __align__(256) int g_cursor[NN];         // fill cursors
__device__ __align__(256) int g_csr_src[NE];        // CSR src indices
__device__ __align__(256) int g_bsum[NB_SCAN];      // per-block sums
__device__ __align__(256) int g_boff[NB_SCAN];      // per-block offsets
__device__ int g_ei64;
__device__ int g_b64;

// ---------------- index load that tolerates int32 or int64 -----------------
__device__ __forceinline__ int ldidx(const void* p, long long i, int is64) {
    if (is64) return (int)(((const long long*)p)[i]);
    return ((const int*)p)[i];
}

// ---------------- init: zero counters/pool + dtype detection ----------------
__global__ void init_kernel(const void* ei, const void* batch) {
    int i = blockIdx.x * blockDim.x + threadIdx.x;
    if (i < NN) g_cnt[i] = 0;
    if (i < NG * 16) g_pool[i] = 0.0f;
    if (i == 0) {
        const unsigned long long* pe = (const unsigned long long*)ei;
        int big = 0;
        for (int k = 0; k < 8; k++) if (pe[k] > 0xFFFFFFFFull) big = 1;
        g_ei64 = big ? 0 : 1;
        const unsigned long long* pb = (const unsigned long long*)batch;
        int big2 = 0;
        for (int k = 0; k < 8; k++) if (pb[20000 + k] > 0xFFFFFFFFull) big2 = 1;
        g_b64 = big2 ? 0 : 1;
    }
}

// ---------------- CSR build -------------------------------------------------
__global__ void hist_kernel(const void* __restrict__ ei) {
    int e = blockIdx.x * blockDim.x + threadIdx.x;
    if (e >= NE) return;
    int d = ldidx(ei, (long long)NE + e, g_ei64);
    atomicAdd(&g_cnt[d], 1);
}

// per-block sums of g_cnt
__global__ void scan1_kernel() {
    __shared__ int sh[256];
    int i = blockIdx.x * 256 + threadIdx.x;
    int v = (i < NN) ? g_cnt[i] : 0;
    sh[threadIdx.x] = v;
    __syncthreads();
    for (int s = 128; s > 0; s >>= 1) {
        if (threadIdx.x < s) sh[threadIdx.x] += sh[threadIdx.x + s];
        __syncthreads();
    }
    if (threadIdx.x == 0) g_bsum[blockIdx.x] = sh[0];
}

// exclusive scan of block sums (single block, 512 threads, NB_SCAN<=512)
__global__ void scan2_kernel() {
    __shared__ int a[512], b[512];
    int t = threadIdx.x;
    int v = (t < NB_SCAN) ? g_bsum[t] : 0;
    a[t] = v;
    __syncthreads();
    int* in = a; int* out = b;
    for (int s = 1; s < 512; s <<= 1) {
        out[t] = in[t] + ((t >= s) ? in[t - s] : 0);
        __syncthreads();
        int* tmp = in; in = out; out = tmp;
    }
    if (t < NB_SCAN) g_boff[t] = in[t] - v;   // exclusive
}

// rowptr/cursor/dis; also fused prep: y = dis*x (padded float4)
__global__ void scan3_kernel(const float* __restrict__ x) {
    __shared__ int a[256], b[256];
    int t = threadIdx.x;
    int i = blockIdx.x * 256 + t;
    int v = (i < NN) ? g_cnt[i] : 0;
    a[t] = v;
    __syncthreads();
    int* in = a; int* out = b;
    for (int s = 1; s < 256; s <<= 1) {
        out[t] = in[t] + ((t >= s) ? in[t - s] : 0);
        __syncthreads();
        int* tmp = in; in = out; out = tmp;
    }
    if (i < NN) {
        int rp = g_boff[blockIdx.x] + in[t] - v;
        g_rowptr[i] = rp;
        g_cursor[i] = rp;
        float di = rsqrtf((float)(v + 1));
        g_dis[i] = di;
        float4 y;
        y.x = di * x[3 * i + 0];
        y.y = di * x[3 * i + 1];
        y.z = di * x[3 * i + 2];
        y.w = 0.0f;
        g_y4[i] = y;
    }
}

__global__ void fill_kernel(const void* __restrict__ ei) {
    int e = blockIdx.x * blockDim.x + threadIdx.x;
    if (e >= NE) return;
    int is64 = g_ei64;
    int s = ldidx(ei, e, is64);
    int d = ldidx(ei, (long long)NE + e, is64);
    int pos = atomicAdd(&g_cursor[d], 1);
    g_csr_src[pos] = s;
}

// ---------------- gathers (warp per node, no atomics) -----------------------
__global__ void gather4_kernel() {
    int node = (blockIdx.x * blockDim.x + threadIdx.x) >> 5;
    int lane = threadIdx.x & 31;
    if (node >= NN) return;
    int base = g_rowptr[node];
    int n = g_cnt[node];
    float3 acc = make_float3(0.f, 0.f, 0.f);
    for (int e = lane; e < n; e += 32) {
        int s = __ldg(&g_csr_src[base + e]);
        float4 v = __ldg(&g_y4[s]);
        acc.x += v.x; acc.y += v.y; acc.z += v.z;
    }
#pragma unroll
    for (int s = 16; s > 0; s >>= 1) {
        acc.x += __shfl_xor_sync(0xFFFFFFFFu, acc.x, s);
        acc.y += __shfl_xor_sync(0xFFFFFFFFu, acc.y, s);
        acc.z += __shfl_xor_sync(0xFFFFFFFFu, acc.z, s);
    }
    if (lane == 0) {
        float4 self = g_y4[node];
        float4 o;
        o.x = acc.x + self.x; o.y = acc.y + self.y; o.z = acc.z + self.z; o.w = 0.f;
        g_agg4[node] = o;
    }
}

// 16-wide gather: agg[i] = sum_{src in-edges} t'[src] + t'[i]
__global__ void gather16_kernel() {
    int node = (blockIdx.x * blockDim.x + threadIdx.x) >> 5;
    int lane = threadIdx.x & 31;
    if (node >= NN) return;
    int base = g_rowptr[node];
    int n = g_cnt[node];
    int grp = lane >> 2;     // 8 edge groups
    int j = lane & 3;        // float4 component block
    float4 acc = make_float4(0.f, 0.f, 0.f, 0.f);
    for (int e = grp; e < n; e += 8) {
        int s = __ldg(&g_csr_src[base + e]);
        float4 v = __ldg((const float4*)(g_t + 16 * s + 4 * j));
        acc.x += v.x; acc.y += v.y; acc.z += v.z; acc.w += v.w;
    }
#pragma unroll
    for (int s = 4; s < 32; s <<= 1) {
        acc.x += __shfl_xor_sync(0xFFFFFFFFu, acc.x, s);
        acc.y += __shfl_xor_sync(0xFFFFFFFFu, acc.y, s);
        acc.z += __shfl_xor_sync(0xFFFFFFFFu, acc.z, s);
        acc.w += __shfl_xor_sync(0xFFFFFFFFu, acc.w, s);
    }
    if (lane < 4) {
        float4 self = *(const float4*)(g_t + 16 * node + 4 * j);
        acc.x += self.x; acc.y += self.y; acc.z += self.z; acc.w += self.w;
        *(float4*)(g_agg + 16 * node + 4 * j) = acc;
    }
}

// ---------------- transforms -------------------------------------------------
// p = dis*agg4; h1 = relu(p@W1^T+b1) [3->32]; t = h1@W2^T [32->16]; t' = dis*t
__global__ void xform12_kernel(const float* __restrict__ W1, const float* __restrict__ b1,
                               const float* __restrict__ W2) {
    int i = blockIdx.x * blockDim.x + threadIdx.x;
    if (i >= NN) return;
    float di = g_dis[i];
    float4 a = g_agg4[i];
    float p0 = di * a.x, p1 = di * a.y, p2 = di * a.z;
    float h[32];
#pragma unroll
    for (int o = 0; o < 32; o++) {
        float v = __ldg(&b1[o])
                + p0 * __ldg(&W1[o * 3 + 0])
                + p1 * __ldg(&W1[o * 3 + 1])
                + p2 * __ldg(&W1[o * 3 + 2]);
        h[o] = fmaxf(v, 0.0f);
    }
#pragma unroll
    for (int o = 0; o < 16; o++) {
        float v = 0.0f;
#pragma unroll
        for (int k = 0; k < 32; k++) v += h[k] * __ldg(&W2[o * 32 + k]);
        g_t[16 * i + o] = di * v;
    }
}

// layer-2 combine: h = relu(dis*agg + b2); t = h@W3^T; t' = dis*t
__global__ void combine_xform_kernel(const float* __restrict__ b, const float* __restrict__ W) {
    int i = blockIdx.x * blockDim.x + threadIdx.x;
    if (i >= NN) return;
    float di = g_dis[i];
    float h[16];
#pragma unroll
    for (int o = 0; o < 16; o++)
        h[o] = fmaxf(di * g_agg[16 * i + o] + __ldg(&b[o]), 0.0f);
#pragma unroll
    for (int o = 0; o < 16; o++) {
        float v = 0.0f;
#pragma unroll
        for (int k = 0; k < 16; k++) v += h[k] * __ldg(&W[o * 16 + k]);
        g_t[16 * i + o] = di * v;
    }
}

// layer-3 combine fused with pooling: h = relu(dis*agg + b3);
// g_pool[batch[i]] += h  (vector reductions; batch grouping is dense)
__global__ void combine_pool_kernel(const float* __restrict__ b, const void* __restrict__ batch) {
    int i = blockIdx.x * blockDim.x + threadIdx.x;
    if (i >= NN) return;
    float di = g_dis[i];
    int g = ldidx(batch, i, g_b64);
    float* dst = g_pool + 16 * g;
#pragma unroll
    for (int jb = 0; jb < 4; jb++) {
        float4 a = *(const float4*)(g_agg + 16 * i + 4 * jb);
        float h0 = fmaxf(di * a.x + __ldg(&b[4 * jb + 0]), 0.0f);
        float h1 = fmaxf(di * a.y + __ldg(&b[4 * jb + 1]), 0.0f);
        float h2 = fmaxf(di * a.z + __ldg(&b[4 * jb + 2]), 0.0f);
        float h3 = fmaxf(di * a.w + __ldg(&b[4 * jb + 3]), 0.0f);
        asm volatile("red.global.add.v4.f32 [%0], {%1,%2,%3,%4};"
                     :: "l"(dst + 4 * jb), "f"(h0), "f"(h1), "f"(h2), "f"(h3)
                     : "memory");
    }
}

// ---------------- head ------------------------------------------------------
__global__ void head_kernel(const float* __restrict__ We, const float* __restrict__ be,
                            const float* __restrict__ Wc, const float* __restrict__ bc,
                            float* __restrict__ out) {
    int g = blockIdx.x * blockDim.x + threadIdx.x;
    if (g >= NG) return;
    float p[16];
#pragma unroll
    for (int k = 0; k < 16; k++) p[k] = g_pool[g * 16 + k];
    float dot = 0.0f;
#pragma unroll
    for (int o = 0; o < 16; o++) {
        float v = __ldg(&be[o]);
#pragma unroll
        for (int k = 0; k < 16; k++) v += p[k] * __ldg(&We[o * 16 + k]);
        out[g * 16 + o] = v;
        dot += fmaxf(v, 0.0f) * __ldg(&Wc[o]);
    }
    out[NG * 16 + g] = dot + __ldg(&bc[0]);
}

// ---------------- launch ----------------------------------------------------
extern "C" void kernel_launch(void* const* d_in, const int* in_sizes, int n_in,
                              void* d_out, int out_size) {
    const float* x   = (const float*)d_in[0];
    const void*  ei  = d_in[1];
    const void*  bat = d_in[2];
    const float* W1 = (const float*)d_in[3];
    const float* b1 = (const float*)d_in[4];
    const float* W2 = (const float*)d_in[5];
    const float* b2 = (const float*)d_in[6];
    const float* W3 = (const float*)d_in[7];
    const float* b3 = (const float*)d_in[8];
    const float* We = (const float*)d_in[9];
    const float* be = (const float*)d_in[10];
    const float* Wc = (const float*)d_in[11];
    const float* bc = (const float*)d_in[12];
    float* out = (float*)d_out;

    const int TB = 256;
    const int gN = (NN + TB - 1) / TB;           // node grid
    const int gE = (NE + TB - 1) / TB;           // edge grid
    const int gW = (NN * 32 + TB - 1) / TB;      // warp-per-node grid

    // init (zero cnt+pool, detect dtypes)
    init_kernel<<<gN, TB>>>(ei, bat);

    // CSR build (also yields dis and pre-scaled y4)
    hist_kernel<<<gE, TB>>>(ei);
    scan1_kernel<<<NB_SCAN, 256>>>();
    scan2_kernel<<<1, 512>>>();
    scan3_kernel<<<NB_SCAN, 256>>>(x);
    fill_kernel<<<gE, TB>>>(ei);

    // layer 1: commuted propagation of pre-scaled raw features
    gather4_kernel<<<gW, TB>>>();
    xform12_kernel<<<gN, TB>>>(W1, b1, W2);

    // layer 2
    gather16_kernel<<<gW, TB>>>();
    combine_xform_kernel<<<gN, TB>>>(b2, W3);

    // layer 3 (combine fused with pooling)
    gather16_kernel<<<gW, TB>>>();
    combine_pool_kernel<<<gN, TB>>>(b3, bat);

    // heads
    head_kernel<<<(NG + TB - 1) / TB, TB>>>(We, be, Wc, bc, out);
}